// round 11
// baseline (speedup 1.0000x reference)
#include <cuda_runtime.h>
#include <cuda_fp16.h>
#include <cstdint>

// ============================================================================
// GptOssMoEExperts: router collapses to identity (softmax over top-k sums to 1
// and the expert MLP is shared), so
//   out = ((x@Wg^T+bg) * silu(x@Wu^T+bu)) @ W2^T + b2
// Structure: cvt fp32->fp16, GEMM1 (x@W1^T+b1 -> gateup fp16), SiLU, GEMM2.
// Base (R10): 4-stage cp.async, cross-kt fragment prefetch, interleaved LDGSTS
// quarters, strength-reduced addressing, 2 CTA/SM. GEMM1 tensor=80.5%.
// R11 change: GEMM2 tile BN 96->64 for wave quantization. GEMM2 grid was
// 960 CTAs / 296 concurrent = 3.24 -> 4 waves (eff 0.81); BN=64 gives grid
// 1440 -> 4.86 -> 5 waves (eff 0.97), outweighing the slightly worse
// ldsm/MMA ratio of the 64x32 warp tile. GEMM1 stays BN=96 (6.49->7, 0.93).
// ============================================================================

#define SEQ   4096
#define HID   2880
#define INTER 2880
#define NGU   (2 * INTER)   // 5760

static constexpr int BM     = 128;
static constexpr int BK     = 64;            // fp16 elems -> 128B rows
static constexpr int KIT    = HID / BK;      // 45
static constexpr int STAGES = 4;
static constexpr int OFF_B  = BM * 128;      // 16384

// ---------------------------------------------------------------------------
// Scratch (__device__ globals = sanctioned allocation-free scratch)
// ---------------------------------------------------------------------------
__device__ __align__(128) __half g_xh [(size_t)SEQ * HID];
__device__ __align__(128) __half g_w1h[(size_t)NGU * HID];
__device__ __align__(128) __half g_w2h[(size_t)HID * INTER];
__device__ __align__(128) __half g_gu [(size_t)SEQ * NGU];
__device__ __align__(128) __half g_hh [(size_t)SEQ * INTER];

// ---------------------------------------------------------------------------
// PTX helpers
// ---------------------------------------------------------------------------
__device__ __forceinline__ uint32_t smem_u32(const void* p) {
    uint32_t a;
    asm("{ .reg .u64 t; cvta.to.shared.u64 t, %1; cvt.u32.u64 %0, t; }" : "=r"(a) : "l"(p));
    return a;
}
__device__ __forceinline__ void ldsm4(uint32_t* r, uint32_t a) {
    asm volatile("ldmatrix.sync.aligned.m8n8.x4.shared.b16 {%0,%1,%2,%3}, [%4];"
                 : "=r"(r[0]), "=r"(r[1]), "=r"(r[2]), "=r"(r[3]) : "r"(a));
}
__device__ __forceinline__ void mma16816(float* d, const uint32_t* a, const uint32_t* b) {
    asm volatile(
        "mma.sync.aligned.m16n8k16.row.col.f32.f16.f16.f32 "
        "{%0,%1,%2,%3}, {%4,%5,%6,%7}, {%8,%9}, {%0,%1,%2,%3};"
        : "+f"(d[0]), "+f"(d[1]), "+f"(d[2]), "+f"(d[3])
        : "r"(a[0]), "r"(a[1]), "r"(a[2]), "r"(a[3]), "r"(b[0]), "r"(b[1]));
}
__device__ __forceinline__ void cp16(uint32_t s, const void* g) {
    asm volatile("cp.async.cg.shared.global [%0], [%1], 16;" :: "r"(s), "l"(g) : "memory");
}
#define CP_COMMIT()  asm volatile("cp.async.commit_group;" ::: "memory")
#define CP_WAIT_1()  asm volatile("cp.async.wait_group 1;"  ::: "memory")

// ---------------------------------------------------------------------------
// fp32 -> fp16 conversion (vectorized)
// ---------------------------------------------------------------------------
__global__ void cvt_kernel(const float4* __restrict__ src, uint2* __restrict__ dst, int n4) {
    int i = blockIdx.x * blockDim.x + threadIdx.x;
    if (i >= n4) return;
    float4 v = src[i];
    __half2 a = __floats2half2_rn(v.x, v.y);
    __half2 b = __floats2half2_rn(v.z, v.w);
    uint2 o;
    o.x = *reinterpret_cast<uint32_t*>(&a);
    o.y = *reinterpret_cast<uint32_t*>(&b);
    dst[i] = o;
}

// ---------------------------------------------------------------------------
// Elementwise SiLU-mul: h[r,c] = gu[r,c] * silu(gu[r,INTER+c]), 8 elems/thread
// ---------------------------------------------------------------------------
__global__ void silu_kernel(const __half* __restrict__ gu, __half* __restrict__ h) {
    const int i = blockIdx.x * blockDim.x + threadIdx.x;
    const int n8 = SEQ * INTER / 8;
    if (i >= n8) return;
    const int r  = i / (INTER / 8);
    const int c8 = i % (INTER / 8);
    const uint4 gv = *reinterpret_cast<const uint4*>(gu + (size_t)r * NGU + c8 * 8);
    const uint4 uv = *reinterpret_cast<const uint4*>(gu + (size_t)r * NGU + INTER + c8 * 8);
    const __half2* gp = reinterpret_cast<const __half2*>(&gv);
    const __half2* up = reinterpret_cast<const __half2*>(&uv);
    uint4 ov;
    __half2* op = reinterpret_cast<__half2*>(&ov);
    #pragma unroll
    for (int k = 0; k < 4; k++) {
        float2 g = __half22float2(gp[k]);
        float2 u = __half22float2(up[k]);
        float h0 = g.x * u.x * (1.0f / (1.0f + __expf(-u.x)));
        float h1 = g.y * u.y * (1.0f / (1.0f + __expf(-u.y)));
        op[k] = __floats2half2_rn(h0, h1);
    }
    *reinterpret_cast<uint4*>(h + (size_t)r * INTER + c8 * 8) = ov;
}

// ---------------------------------------------------------------------------
// Pipelined fp16 GEMM:  C[BM x BNT] = A[BM x K] * B[BNT x K]^T + bias
//   HALF_OUT=true : store fp16, false: fp32.  BNT in {96, 64}.
// 128 threads = 4 warps (2M x 2N); warp tile 64 x (BNT/2).
// 4-stage cp.async, wait_group 1, cross-kt register-fragment prefetch,
// LDGSTS interleaved per ks with strength-reduced addressing, 2 CTAs/SM.
// ---------------------------------------------------------------------------
template <bool HALF_OUT, int BNT>
__global__ void __launch_bounds__(128, 2)
gemm_f16(const __half* __restrict__ A, const __half* __restrict__ B,
         const float* __restrict__ bias,
         __half* __restrict__ oH, float* __restrict__ oF, int ldo) {
    constexpr int STG  = OFF_B + BNT * 128;       // stage bytes
    constexpr int NFB  = BNT / 32;                // B ldsm4 per ks (3 or 2)
    constexpr int NJ   = 2 * NFB;                 // n8 frags per warp (6 or 4)

    extern __shared__ __align__(128) char smem[];
    const uint32_t sb0 = smem_u32(smem);
    const int tid = threadIdx.x;
    const int l   = tid & 31;
    const int wid = tid >> 5;          // 0..3
    const int wm  = wid >> 1;          // 0..1
    const int wn  = wid & 1;           // 0..1
    const int mBase = blockIdx.x * BM;
    const int nBase = blockIdx.y * BNT;

    // ---- strength-reduced cp.async addressing ----
    const int rowT = tid >> 3;                    // 0..15
    const int u8   = tid & 7;
    const uint32_t aSmem = (uint32_t)rowT * 128 + (uint32_t)((u8 ^ (rowT & 7)) << 4);
    const uint32_t bSmem = OFF_B + aSmem;
    const __half* gAn = A + (size_t)(mBase + rowT) * HID + u8 * 8;
    const __half* gBn = B + (size_t)(nBase + rowT) * HID + u8 * 8;

    // One quarter of a stage's loads.
    auto load_part = [&](uint32_t sbSlot, int part) {
        #pragma unroll
        for (int k = 2 * part; k < 2 * part + 2; k++)         // A: 2 chunks
            cp16(sbSlot + aSmem + k * 2048, gAn + (size_t)k * 16 * HID);
        if constexpr (BNT == 96) {                            // B: 6 chunks tot
            if (part < 2) {
                #pragma unroll
                for (int k = 2 * part; k < 2 * part + 2; k++)
                    cp16(sbSlot + bSmem + k * 2048, gBn + (size_t)k * 16 * HID);
            } else {
                const int k = part + 2;
                cp16(sbSlot + bSmem + k * 2048, gBn + (size_t)k * 16 * HID);
            }
        } else {                                              // BNT==64: 4 tot
            cp16(sbSlot + bSmem + part * 2048, gBn + (size_t)part * 16 * HID);
        }
    };

    const int l7  = l & 7;
    const int lhi = l >> 4;
    const int le  = l & 15;
    const int q   = l >> 3;
    const int aRow0 = wm * 64 + le;
    const int bRowO = wn * (BNT / 2) + ((q >> 1) << 3) + l7;
    const int bUnit = q & 1;

    auto loadA = [&](uint32_t af[4][4], uint32_t sA, int ks) {
        #pragma unroll
        for (int i = 0; i < 4; i++)
            ldsm4(af[i], sA + (uint32_t)(aRow0 + i * 16) * 128 +
                           (uint32_t)(((ks * 2 + lhi) ^ l7) << 4));
    };
    auto loadB = [&](uint32_t bf[NFB][4], uint32_t sB, int ks) {
        #pragma unroll
        for (int p = 0; p < NFB; p++)
            ldsm4(bf[p], sB + (uint32_t)(bRowO + p * 16) * 128 +
                           (uint32_t)(((ks * 2 + bUnit) ^ l7) << 4));
    };

    float acc[4][NJ][4] = {};
    uint32_t af[2][4][4], bf[2][NFB][4];

    #pragma unroll
    for (int s = 0; s < STAGES - 1; s++) {                // prologue: 3 stages
        const uint32_t sbSlot = sb0 + s * STG;
        #pragma unroll
        for (int p = 0; p < 4; p++) load_part(sbSlot, p);
        CP_COMMIT();
        gAn += BK;  gBn += BK;
    }

    // Peeled head: stages 0 and 1 resident after this wait.
    CP_WAIT_1();
    __syncthreads();
    loadA(af[0], sb0, 0);
    loadB(bf[0], sb0 + OFF_B, 0);

    for (int kt = 0; kt < KIT; kt++) {
        const int  nk     = kt + STAGES - 1;
        const bool doLoad = nk < KIT;
        const uint32_t sbSlot = sb0 + (nk % STAGES) * STG;

        const uint32_t sA  = sb0 + (kt % STAGES) * STG;
        const uint32_t sB  = sA + OFF_B;
        const uint32_t sAn = sb0 + ((kt + 1) % STAGES) * STG;   // next tile
        const uint32_t sBn = sAn + OFF_B;

        #pragma unroll
        for (int ks = 0; ks < 4; ks++) {
            const int cur = ks & 1, nxt = cur ^ 1;
            if (ks < 3) {
                loadA(af[nxt], sA, ks + 1);
                loadB(bf[nxt], sB, ks + 1);
            } else if (kt + 1 < KIT) {
                loadA(af[nxt], sAn, 0);       // cross-kt prefetch
                loadB(bf[nxt], sBn, 0);
            }
            if (doLoad) load_part(sbSlot, ks);
            #pragma unroll
            for (int i = 0; i < 4; i++)
                #pragma unroll
                for (int p = 0; p < NFB; p++) {
                    mma16816(acc[i][2 * p],     af[cur][i], &bf[cur][p][0]);
                    mma16816(acc[i][2 * p + 1], af[cur][i], &bf[cur][p][2]);
                }
        }
        CP_COMMIT();
        gAn += BK;  gBn += BK;
        if (kt + 1 < KIT) {
            CP_WAIT_1();
            __syncthreads();
        }
    }

    // ------------------------------- epilogue -------------------------------
    const int r00 = mBase + wm * 64 + (l >> 2);
    const int cB  = nBase + wn * (BNT / 2) + 2 * (l & 3);

    #pragma unroll
    for (int i = 0; i < 4; i++)
        #pragma unroll
        for (int j = 0; j < NJ; j++) {
            const int c = cB + j * 8;
            const float b0 = __ldg(bias + c), b1 = __ldg(bias + c + 1);
            #pragma unroll
            for (int hh = 0; hh < 2; hh++) {
                const int r = r00 + i * 16 + hh * 8;
                const float v0 = acc[i][j][2 * hh]     + b0;
                const float v1 = acc[i][j][2 * hh + 1] + b1;
                if constexpr (HALF_OUT) {
                    *reinterpret_cast<__half2*>(oH + (size_t)r * ldo + c) =
                        __floats2half2_rn(v0, v1);
                } else {
                    *reinterpret_cast<float2*>(oF + (size_t)r * ldo + c) =
                        make_float2(v0, v1);
                }
            }
        }
}

// ---------------------------------------------------------------------------
// Host
// ---------------------------------------------------------------------------
extern "C" void kernel_launch(void* const* d_in, const int* in_sizes, int n_in,
                              void* d_out, int out_size) {
    const float* x  = (const float*)d_in[0];   // hidden_states (4096, 2880)
    const float* w1 = (const float*)d_in[3];   // gate_up_w (5760, 2880)
    const float* b1 = (const float*)d_in[4];   // gate_up_b (5760,)
    const float* w2 = (const float*)d_in[5];   // down_w (2880, 2880)
    const float* b2 = (const float*)d_in[6];   // down_b (2880,)
    float* out = (float*)d_out;                // (4096, 2880) fp32

    void *px, *pw1, *pw2, *pgu, *ph;
    cudaGetSymbolAddress(&px,  g_xh);
    cudaGetSymbolAddress(&pw1, g_w1h);
    cudaGetSymbolAddress(&pw2, g_w2h);
    cudaGetSymbolAddress(&pgu, g_gu);
    cudaGetSymbolAddress(&ph,  g_hh);

    // fp32 -> fp16
    {
        int n4 = (SEQ * HID) / 4;
        cvt_kernel<<<(n4 + 255) / 256, 256>>>((const float4*)x,  (uint2*)px,  n4);
        n4 = (NGU * HID) / 4;
        cvt_kernel<<<(n4 + 255) / 256, 256>>>((const float4*)w1, (uint2*)pw1, n4);
        n4 = (HID * INTER) / 4;
        cvt_kernel<<<(n4 + 255) / 256, 256>>>((const float4*)w2, (uint2*)pw2, n4);
    }

    constexpr int SMEM_96 = STAGES * (OFF_B + 96 * 128);   // 114688
    constexpr int SMEM_64 = STAGES * (OFF_B + 64 * 128);   // 98304
    cudaFuncSetAttribute((const void*)gemm_f16<true, 96>,
                         cudaFuncAttributeMaxDynamicSharedMemorySize, SMEM_96);
    cudaFuncSetAttribute((const void*)gemm_f16<false, 64>,
                         cudaFuncAttributeMaxDynamicSharedMemorySize, SMEM_64);

    // GEMM1: gateup = x @ W1^T + b1   (fp16, 4096 x 5760)
    gemm_f16<true, 96><<<dim3(SEQ / BM, NGU / 96), 128, SMEM_96>>>(
        (const __half*)px, (const __half*)pw1, b1, (__half*)pgu, nullptr, NGU);

    // SiLU: h = gate * silu(up)   (fp16, 4096 x 2880)
    {
        int n8 = SEQ * INTER / 8;
        silu_kernel<<<(n8 + 255) / 256, 256>>>((const __half*)pgu, (__half*)ph);
    }

    // GEMM2: out = h @ W2^T + b2   (fp32, 4096 x 2880)
    gemm_f16<false, 64><<<dim3(SEQ / BM, HID / 64), 128, SMEM_64>>>(
        (const __half*)ph, (const __half*)pw2, b2, nullptr, out, HID);
}

// round 12
// speedup vs baseline: 1.0079x; 1.0079x over previous
#include <cuda_runtime.h>
#include <cuda_fp16.h>
#include <cstdint>

// ============================================================================
// GptOssMoEExperts: router collapses to identity (softmax over top-k sums to 1
// and the expert MLP is shared), so
//   out = ((x@Wg^T+bg) * silu(x@Wu^T+bu)) @ W2^T + b2
// R12: GEMM1 fuses SiLU via REGISTER pairing: 4 M-warps (warp tile 32x96) span
// the whole B tile = [48 gate rows | 48 up rows of the SAME 48 out cols], so
// acc[i][j] (gate) pairs with acc[i][j+6] (up) in registers -> h fp16 directly.
// No smem exchange, no extra sync (unlike the failed R5/R7 fusions).
// GEMM2 reverted to the proven BN=96 / 64x48 config.
// Both GEMMs: 4-stage cp.async, cross-kt fragment prefetch, interleaved LDGSTS
// quarters, strength-reduced addressing, 2 CTA/SM.
// ============================================================================

#define SEQ   4096
#define HID   2880
#define INTER 2880
#define NGU   (2 * INTER)   // 5760

static constexpr int BM     = 128;
static constexpr int BN     = 96;            // B-tile rows (both GEMMs)
static constexpr int BK     = 64;            // fp16 elems -> 128B rows
static constexpr int KIT    = HID / BK;      // 45
static constexpr int STAGES = 4;
static constexpr int OFF_B  = BM * 128;               // 16384
static constexpr int STAGE  = OFF_B + BN * 128;       // 28672
static constexpr int SMEM_SZ = STAGES * STAGE;        // 114688 (x2 = 224KB/SM)

// ---------------------------------------------------------------------------
// Scratch (__device__ globals = sanctioned allocation-free scratch)
// ---------------------------------------------------------------------------
__device__ __align__(128) __half g_xh [(size_t)SEQ * HID];
__device__ __align__(128) __half g_w1h[(size_t)NGU * HID];
__device__ __align__(128) __half g_w2h[(size_t)HID * INTER];
__device__ __align__(128) __half g_hh [(size_t)SEQ * INTER];

// ---------------------------------------------------------------------------
// PTX helpers
// ---------------------------------------------------------------------------
__device__ __forceinline__ uint32_t smem_u32(const void* p) {
    uint32_t a;
    asm("{ .reg .u64 t; cvta.to.shared.u64 t, %1; cvt.u32.u64 %0, t; }" : "=r"(a) : "l"(p));
    return a;
}
__device__ __forceinline__ void ldsm4(uint32_t* r, uint32_t a) {
    asm volatile("ldmatrix.sync.aligned.m8n8.x4.shared.b16 {%0,%1,%2,%3}, [%4];"
                 : "=r"(r[0]), "=r"(r[1]), "=r"(r[2]), "=r"(r[3]) : "r"(a));
}
__device__ __forceinline__ void mma16816(float* d, const uint32_t* a, const uint32_t* b) {
    asm volatile(
        "mma.sync.aligned.m16n8k16.row.col.f32.f16.f16.f32 "
        "{%0,%1,%2,%3}, {%4,%5,%6,%7}, {%8,%9}, {%0,%1,%2,%3};"
        : "+f"(d[0]), "+f"(d[1]), "+f"(d[2]), "+f"(d[3])
        : "r"(a[0]), "r"(a[1]), "r"(a[2]), "r"(a[3]), "r"(b[0]), "r"(b[1]));
}
__device__ __forceinline__ void cp16(uint32_t s, const void* g) {
    asm volatile("cp.async.cg.shared.global [%0], [%1], 16;" :: "r"(s), "l"(g) : "memory");
}
#define CP_COMMIT()  asm volatile("cp.async.commit_group;" ::: "memory")
#define CP_WAIT_1()  asm volatile("cp.async.wait_group 1;"  ::: "memory")

// ---------------------------------------------------------------------------
// fp32 -> fp16 conversion (vectorized)
// ---------------------------------------------------------------------------
__global__ void cvt_kernel(const float4* __restrict__ src, uint2* __restrict__ dst, int n4) {
    int i = blockIdx.x * blockDim.x + threadIdx.x;
    if (i >= n4) return;
    float4 v = src[i];
    __half2 a = __floats2half2_rn(v.x, v.y);
    __half2 b = __floats2half2_rn(v.z, v.w);
    uint2 o;
    o.x = *reinterpret_cast<uint32_t*>(&a);
    o.y = *reinterpret_cast<uint32_t*>(&b);
    dst[i] = o;
}

// ---------------------------------------------------------------------------
// GEMM1 (register-paired SiLU fusion):
//   h[:, nBase:nBase+48] = (x@Wg^T+bg) * silu(x@Wu^T+bu)
// B tile rows 0-47 = W1 rows nBase.. (gate), rows 48-95 = W1 rows INTER+nBase..
// (up, same output cols). 4 M-warps, warp tile 32x96: acc[i][j] gate pairs
// with acc[i][j+6] up in the same thread.
// ---------------------------------------------------------------------------
__global__ void __launch_bounds__(128, 2)
gemm1_fused(const __half* __restrict__ A, const __half* __restrict__ W1,
            const float* __restrict__ b1, __half* __restrict__ h) {
    extern __shared__ __align__(128) char smem[];
    const uint32_t sb0 = smem_u32(smem);
    const int tid = threadIdx.x;
    const int l   = tid & 31;
    const int wm  = tid >> 5;          // 0..3 (all M-warps)
    const int mBase = blockIdx.x * BM;
    const int nBase = blockIdx.y * 48;  // 48 output cols per CTA

    // ---- strength-reduced cp.async addressing ----
    const int rowT = tid >> 3;                    // 0..15
    const int u8   = tid & 7;
    const uint32_t aSmem = (uint32_t)rowT * 128 + (uint32_t)((u8 ^ (rowT & 7)) << 4);
    const uint32_t bSmem = OFF_B + aSmem;
    const __half* gAn = A  + (size_t)(mBase + rowT) * HID + u8 * 8;
    const __half* gBg = W1 + (size_t)(nBase + rowT) * HID + u8 * 8;          // gate rows
    const __half* gBu = W1 + (size_t)(INTER + nBase + rowT) * HID + u8 * 8;  // up rows

    // B chunk k (k=0..5): rows rowT+16k. k<3 -> gate, k>=3 -> up (k-3).
    auto bptr = [&](int k) -> const __half* {
        return (k < 3) ? gBg + (size_t)k * 16 * HID
                       : gBu + (size_t)(k - 3) * 16 * HID;
    };
    // One quarter of a stage's loads: 2 A chunks + (2|1) B chunks.
    auto load_part = [&](uint32_t sbSlot, int part) {
        #pragma unroll
        for (int k = 2 * part; k < 2 * part + 2; k++)         // A chunks
            cp16(sbSlot + aSmem + k * 2048, gAn + (size_t)k * 16 * HID);
        if (part < 2) {                                       // B chunks 0-3
            #pragma unroll
            for (int k = 2 * part; k < 2 * part + 2; k++)
                cp16(sbSlot + bSmem + k * 2048, bptr(k));
        } else {                                              // B chunks 4-5
            const int k = part + 2;
            cp16(sbSlot + bSmem + k * 2048, bptr(k));
        }
    };

    const int l7  = l & 7;
    const int lhi = l >> 4;
    const int le  = l & 15;
    const int q   = l >> 3;
    const int aRow0 = wm * 32 + le;
    const int bRowO = ((q >> 1) << 3) + l7;
    const int bUnit = q & 1;

    auto loadA = [&](uint32_t af[2][4], uint32_t sA, int ks) {
        #pragma unroll
        for (int i = 0; i < 2; i++)
            ldsm4(af[i], sA + (uint32_t)(aRow0 + i * 16) * 128 +
                           (uint32_t)(((ks * 2 + lhi) ^ l7) << 4));
    };
    auto loadB = [&](uint32_t bf[6][4], uint32_t sB, int ks) {
        #pragma unroll
        for (int p = 0; p < 6; p++)
            ldsm4(bf[p], sB + (uint32_t)(bRowO + p * 16) * 128 +
                           (uint32_t)(((ks * 2 + bUnit) ^ l7) << 4));
    };

    float acc[2][12][4] = {};
    uint32_t af[2][2][4], bf[2][6][4];

    #pragma unroll
    for (int s = 0; s < STAGES - 1; s++) {                // prologue: 3 stages
        const uint32_t sbSlot = sb0 + s * STAGE;
        #pragma unroll
        for (int p = 0; p < 4; p++) load_part(sbSlot, p);
        CP_COMMIT();
        gAn += BK;  gBg += BK;  gBu += BK;
    }

    CP_WAIT_1();
    __syncthreads();
    loadA(af[0], sb0, 0);
    loadB(bf[0], sb0 + OFF_B, 0);

    for (int kt = 0; kt < KIT; kt++) {
        const int  nk     = kt + STAGES - 1;
        const bool doLoad = nk < KIT;
        const uint32_t sbSlot = sb0 + (nk % STAGES) * STAGE;

        const uint32_t sA  = sb0 + (kt % STAGES) * STAGE;
        const uint32_t sB  = sA + OFF_B;
        const uint32_t sAn = sb0 + ((kt + 1) % STAGES) * STAGE;
        const uint32_t sBn = sAn + OFF_B;

        #pragma unroll
        for (int ks = 0; ks < 4; ks++) {
            const int cur = ks & 1, nxt = cur ^ 1;
            if (ks < 3) {
                loadA(af[nxt], sA, ks + 1);
                loadB(bf[nxt], sB, ks + 1);
            } else if (kt + 1 < KIT) {
                loadA(af[nxt], sAn, 0);       // cross-kt prefetch
                loadB(bf[nxt], sBn, 0);
            }
            if (doLoad) load_part(sbSlot, ks);
            #pragma unroll
            for (int i = 0; i < 2; i++)
                #pragma unroll
                for (int p = 0; p < 6; p++) {
                    mma16816(acc[i][2 * p],     af[cur][i], &bf[cur][p][0]);
                    mma16816(acc[i][2 * p + 1], af[cur][i], &bf[cur][p][2]);
                }
        }
        CP_COMMIT();
        gAn += BK;  gBg += BK;  gBu += BK;
        if (kt + 1 < KIT) {
            CP_WAIT_1();
            __syncthreads();
        }
    }

    // ---- epilogue: register-paired SiLU, h fp16 ----
    const int r00 = mBase + wm * 32 + (l >> 2);
    const int cL  = 2 * (l & 3);

    #pragma unroll
    for (int j = 0; j < 6; j++) {                 // gate frag j, up frag j+6
        const int c = cL + j * 8;
        const float bg0 = __ldg(b1 + nBase + c);
        const float bg1 = __ldg(b1 + nBase + c + 1);
        const float bu0 = __ldg(b1 + INTER + nBase + c);
        const float bu1 = __ldg(b1 + INTER + nBase + c + 1);
        #pragma unroll
        for (int i = 0; i < 2; i++)
            #pragma unroll
            for (int hh = 0; hh < 2; hh++) {
                const int r = r00 + i * 16 + hh * 8;
                const float g0 = acc[i][j][2 * hh]         + bg0;
                const float g1 = acc[i][j][2 * hh + 1]     + bg1;
                const float u0 = acc[i][j + 6][2 * hh]     + bu0;
                const float u1 = acc[i][j + 6][2 * hh + 1] + bu1;
                const float h0 = g0 * u0 * (1.0f / (1.0f + __expf(-u0)));
                const float h1 = g1 * u1 * (1.0f / (1.0f + __expf(-u1)));
                *reinterpret_cast<__half2*>(
                    h + (size_t)r * INTER + nBase + c) =
                    __floats2half2_rn(h0, h1);
            }
    }
}

// ---------------------------------------------------------------------------
// GEMM2: out = h @ W2^T + b2 (fp32). CTA 128x96, 4 warps (2Mx2N), warp 64x48.
// (proven R10 config)
// ---------------------------------------------------------------------------
__global__ void __launch_bounds__(128, 2)
gemm2(const __half* __restrict__ A, const __half* __restrict__ B,
      const float* __restrict__ bias, float* __restrict__ oF) {
    extern __shared__ __align__(128) char smem[];
    const uint32_t sb0 = smem_u32(smem);
    const int tid = threadIdx.x;
    const int l   = tid & 31;
    const int wid = tid >> 5;
    const int wm  = wid >> 1;
    const int wn  = wid & 1;
    const int mBase = blockIdx.x * BM;
    const int nBase = blockIdx.y * BN;

    const int rowT = tid >> 3;
    const int u8   = tid & 7;
    const uint32_t aSmem = (uint32_t)rowT * 128 + (uint32_t)((u8 ^ (rowT & 7)) << 4);
    const uint32_t bSmem = OFF_B + aSmem;
    const __half* gAn = A + (size_t)(mBase + rowT) * HID + u8 * 8;
    const __half* gBn = B + (size_t)(nBase + rowT) * HID + u8 * 8;

    auto load_part = [&](uint32_t sbSlot, int part) {
        #pragma unroll
        for (int k = 2 * part; k < 2 * part + 2; k++)
            cp16(sbSlot + aSmem + k * 2048, gAn + (size_t)k * 16 * HID);
        if (part < 2) {
            #pragma unroll
            for (int k = 2 * part; k < 2 * part + 2; k++)
                cp16(sbSlot + bSmem + k * 2048, gBn + (size_t)k * 16 * HID);
        } else {
            const int k = part + 2;
            cp16(sbSlot + bSmem + k * 2048, gBn + (size_t)k * 16 * HID);
        }
    };

    const int l7  = l & 7;
    const int lhi = l >> 4;
    const int le  = l & 15;
    const int q   = l >> 3;
    const int aRow0 = wm * 64 + le;
    const int bRowO = wn * 48 + ((q >> 1) << 3) + l7;
    const int bUnit = q & 1;

    auto loadA = [&](uint32_t af[4][4], uint32_t sA, int ks) {
        #pragma unroll
        for (int i = 0; i < 4; i++)
            ldsm4(af[i], sA + (uint32_t)(aRow0 + i * 16) * 128 +
                           (uint32_t)(((ks * 2 + lhi) ^ l7) << 4));
    };
    auto loadB = [&](uint32_t bf[3][4], uint32_t sB, int ks) {
        #pragma unroll
        for (int p = 0; p < 3; p++)
            ldsm4(bf[p], sB + (uint32_t)(bRowO + p * 16) * 128 +
                           (uint32_t)(((ks * 2 + bUnit) ^ l7) << 4));
    };

    float acc[4][6][4] = {};
    uint32_t af[2][4][4], bf[2][3][4];

    #pragma unroll
    for (int s = 0; s < STAGES - 1; s++) {
        const uint32_t sbSlot = sb0 + s * STAGE;
        #pragma unroll
        for (int p = 0; p < 4; p++) load_part(sbSlot, p);
        CP_COMMIT();
        gAn += BK;  gBn += BK;
    }

    CP_WAIT_1();
    __syncthreads();
    loadA(af[0], sb0, 0);
    loadB(bf[0], sb0 + OFF_B, 0);

    for (int kt = 0; kt < KIT; kt++) {
        const int  nk     = kt + STAGES - 1;
        const bool doLoad = nk < KIT;
        const uint32_t sbSlot = sb0 + (nk % STAGES) * STAGE;

        const uint32_t sA  = sb0 + (kt % STAGES) * STAGE;
        const uint32_t sB  = sA + OFF_B;
        const uint32_t sAn = sb0 + ((kt + 1) % STAGES) * STAGE;
        const uint32_t sBn = sAn + OFF_B;

        #pragma unroll
        for (int ks = 0; ks < 4; ks++) {
            const int cur = ks & 1, nxt = cur ^ 1;
            if (ks < 3) {
                loadA(af[nxt], sA, ks + 1);
                loadB(bf[nxt], sB, ks + 1);
            } else if (kt + 1 < KIT) {
                loadA(af[nxt], sAn, 0);
                loadB(bf[nxt], sBn, 0);
            }
            if (doLoad) load_part(sbSlot, ks);
            #pragma unroll
            for (int i = 0; i < 4; i++)
                #pragma unroll
                for (int p = 0; p < 3; p++) {
                    mma16816(acc[i][2 * p],     af[cur][i], &bf[cur][p][0]);
                    mma16816(acc[i][2 * p + 1], af[cur][i], &bf[cur][p][2]);
                }
        }
        CP_COMMIT();
        gAn += BK;  gBn += BK;
        if (kt + 1 < KIT) {
            CP_WAIT_1();
            __syncthreads();
        }
    }

    const int r00 = mBase + wm * 64 + (l >> 2);
    const int cB  = nBase + wn * 48 + 2 * (l & 3);

    #pragma unroll
    for (int i = 0; i < 4; i++)
        #pragma unroll
        for (int j = 0; j < 6; j++) {
            const int c = cB + j * 8;
            const float b0 = __ldg(bias + c), b1v = __ldg(bias + c + 1);
            #pragma unroll
            for (int hh = 0; hh < 2; hh++) {
                const int r = r00 + i * 16 + hh * 8;
                *reinterpret_cast<float2*>(oF + (size_t)r * HID + c) =
                    make_float2(acc[i][j][2 * hh] + b0,
                                acc[i][j][2 * hh + 1] + b1v);
            }
        }
}

// ---------------------------------------------------------------------------
// Host
// ---------------------------------------------------------------------------
extern "C" void kernel_launch(void* const* d_in, const int* in_sizes, int n_in,
                              void* d_out, int out_size) {
    const float* x  = (const float*)d_in[0];   // hidden_states (4096, 2880)
    const float* w1 = (const float*)d_in[3];   // gate_up_w (5760, 2880)
    const float* b1 = (const float*)d_in[4];   // gate_up_b (5760,)
    const float* w2 = (const float*)d_in[5];   // down_w (2880, 2880)
    const float* b2 = (const float*)d_in[6];   // down_b (2880,)
    float* out = (float*)d_out;                // (4096, 2880) fp32

    void *px, *pw1, *pw2, *ph;
    cudaGetSymbolAddress(&px,  g_xh);
    cudaGetSymbolAddress(&pw1, g_w1h);
    cudaGetSymbolAddress(&pw2, g_w2h);
    cudaGetSymbolAddress(&ph,  g_hh);

    // fp32 -> fp16
    {
        int n4 = (SEQ * HID) / 4;
        cvt_kernel<<<(n4 + 255) / 256, 256>>>((const float4*)x,  (uint2*)px,  n4);
        n4 = (NGU * HID) / 4;
        cvt_kernel<<<(n4 + 255) / 256, 256>>>((const float4*)w1, (uint2*)pw1, n4);
        n4 = (HID * INTER) / 4;
        cvt_kernel<<<(n4 + 255) / 256, 256>>>((const float4*)w2, (uint2*)pw2, n4);
    }

    cudaFuncSetAttribute(gemm1_fused,
                         cudaFuncAttributeMaxDynamicSharedMemorySize, SMEM_SZ);
    cudaFuncSetAttribute(gemm2,
                         cudaFuncAttributeMaxDynamicSharedMemorySize, SMEM_SZ);

    // GEMM1 fused: h = (x@Wg^T+bg) * silu(x@Wu^T+bu)   (fp16, 4096 x 2880)
    gemm1_fused<<<dim3(SEQ / BM, INTER / 48), 128, SMEM_SZ>>>(
        (const __half*)px, (const __half*)pw1, b1, (__half*)ph);

    // GEMM2: out = h @ W2^T + b2   (fp32, 4096 x 2880)
    gemm2<<<dim3(SEQ / BM, HID / BN), 128, SMEM_SZ>>>(
        (const __half*)ph, (const __half*)pw2, b2, out);
}